// round 4
// baseline (speedup 1.0000x reference)
#include <cuda_runtime.h>
#include <cstdint>

#define NF        40960
#define MDIM      256
#define NB        2048
#define ROWS      (2*NB)            // 4096 feature rows (white then black)
#define PARTS     2                 // warps per row
#define HALF_F    (NF/PARTS)        // 20480 floats per half row
#define HALF_VEC4 (HALF_F/4)        // 5120 float4s per half row
#define BATCH     8                 // float4s per lane per batch (32 floats)
#define NBATCH    (HALF_VEC4/32/BATCH)  // 20 batches per half-row warp
#define LIST_CAP  64                // per-(row,half) nonzero capacity (lambda=16)

// Transposed feature-transformer weights: ft_wT[f][m], 40960 x 256 fp32 = 41.9 MB
__device__ float g_ftwT[NF * MDIM];
// Compact nonzero index lists + counts
__device__ int g_list[ROWS * PARTS * LIST_CAP];
__device__ int g_cnt[ROWS * PARTS];

// ---------------------------------------------------------------------------
// Kernel 1: tiled transpose ft_w [256, 40960] -> g_ftwT [40960, 256]
// ---------------------------------------------------------------------------
__global__ __launch_bounds__(256) void transpose_ftw_kernel(const float* __restrict__ ft_w) {
    __shared__ float tile[32][33];
    const int f0 = blockIdx.x * 32;
    const int m0 = blockIdx.y * 32;
    const int t  = threadIdx.x;

    {
        const int m = t >> 3;
        const int q = t & 7;
        const float4 v = *reinterpret_cast<const float4*>(
            ft_w + (size_t)(m0 + m) * NF + f0 + q * 4);
        tile[m][q * 4 + 0] = v.x;
        tile[m][q * 4 + 1] = v.y;
        tile[m][q * 4 + 2] = v.z;
        tile[m][q * 4 + 3] = v.w;
    }
    __syncthreads();
    {
        const int f  = t >> 3;
        const int m4 = t & 7;
        float4 v;
        v.x = tile[m4 * 4 + 0][f];
        v.y = tile[m4 * 4 + 1][f];
        v.z = tile[m4 * 4 + 2][f];
        v.w = tile[m4 * 4 + 3][f];
        *reinterpret_cast<float4*>(
            g_ftwT + (size_t)(f0 + f) * MDIM + m0 + m4 * 4) = v;
    }
}

// ---------------------------------------------------------------------------
// Kernel 2 (Phase A): pure streaming scan -> compact index lists.
// One warp per (row, half). No L2 gathers here: the L1tex FIFO sees only the
// DRAM stream, so nothing inherits head-of-line DRAM latency.
// Integer nonzero test (values are exactly 0.0f / 1.0f).
// ---------------------------------------------------------------------------
__global__ __launch_bounds__(256) void scan_kernel(
    const float* __restrict__ wf,
    const float* __restrict__ bfeat)
{
    const int gw   = (blockIdx.x * blockDim.x + threadIdx.x) >> 5;  // 0..8191
    const int lane = threadIdx.x & 31;
    const int row  = gw >> 1;           // 0..4095
    const int part = gw & 1;

    const float* rowp = (row < NB) ? (wf + (size_t)row * NF)
                                   : (bfeat + (size_t)(row - NB) * NF);
    const uint4* p = reinterpret_cast<const uint4*>(rowp) + part * HALF_VEC4;

    int* list = g_list + ((size_t)row * PARTS + part) * LIST_CAP;
    int cnt = 0;   // warp-uniform

    #pragma unroll 1
    for (int bt = 0; bt < NBATCH; bt++) {
        // streaming loads, evict-first
        uint4 v[BATCH];
        #pragma unroll
        for (int u = 0; u < BATCH; u++)
            v[u] = __ldcs(&p[bt * BATCH * 32 + u * 32 + lane]);

        // per-lane nonzero bitmask: bit (u*4+c) = component c of uint4 u
        unsigned mask = 0u;
        #pragma unroll
        for (int u = 0; u < BATCH; u++) {
            if (v[u].x) mask |= 1u << (u * 4 + 0);
            if (v[u].y) mask |= 1u << (u * 4 + 1);
            if (v[u].z) mask |= 1u << (u * 4 + 2);
            if (v[u].w) mask |= 1u << (u * 4 + 3);
        }

        unsigned bal = __ballot_sync(0xffffffffu, mask != 0u);
        if (bal) {
            const int base0 = part * HALF_F + bt * (BATCH * 128);
            do {
                const int s = __ffs(bal) - 1;
                bal &= bal - 1u;
                unsigned sm = __shfl_sync(0xffffffffu, mask, s);
                do {
                    const int b = __ffs(sm) - 1;
                    sm &= sm - 1u;
                    const int f = base0 + (b >> 2) * 128 + s * 4 + (b & 3);
                    if (lane == 0 && cnt < LIST_CAP) list[cnt] = f;
                    cnt++;
                } while (sm);
            } while (bal);
        }
    }
    if (lane == 0) g_cnt[row * PARTS + part] = (cnt < LIST_CAP) ? cnt : LIST_CAP;
}

// ---------------------------------------------------------------------------
// Kernel 3 (Phase B): gather-accumulate + full MLP tail, one CTA per position.
// Pure L2 traffic (ft_wT rows), perfectly coalesced 1KB per feature.
// ---------------------------------------------------------------------------
__device__ __forceinline__ float clamp01(float x) {
    return fminf(fmaxf(x, 0.0f), 1.0f);
}

__global__ __launch_bounds__(256) void gather_mlp_kernel(
    const float* __restrict__ stm,
    const float* __restrict__ ft_b,
    const float* __restrict__ l1_w,
    const float* __restrict__ l1_b,
    const float* __restrict__ l2_w,
    const float* __restrict__ l2_b,
    const float* __restrict__ l3_w,
    const float* __restrict__ l3_b,
    float* __restrict__ out)
{
    const int b   = blockIdx.x;
    const int tid = threadIdx.x;

    __shared__ int   s_list[4][LIST_CAP];   // segs: 0,1 = white p0,p1; 2,3 = black p0,p1
    __shared__ int   s_cnt[4];
    __shared__ float s_h[512];
    __shared__ float s_l2x[32];

    // cooperative list load: seg = tid>>6, slot = tid&63
    {
        const int seg  = tid >> 6;               // 0..3
        const int slot = tid & 63;
        const int row  = (seg < 2) ? b : (NB + b);
        const int part = seg & 1;
        const size_t base = ((size_t)row * PARTS + part) * LIST_CAP;
        s_list[seg][slot] = g_list[base + slot];
        if (slot == 0) s_cnt[seg] = g_cnt[row * PARTS + part];
    }
    __syncthreads();

    const float bias = ft_b[tid];

    // gather-accumulate: thread tid owns output m = tid
    float accW = bias, accB = bias;
    #pragma unroll
    for (int seg = 0; seg < 4; seg++) {
        const int n = s_cnt[seg];
        float acc = 0.0f;
        int j = 0;
        for (; j + 4 <= n; j += 4) {
            const float a0 = g_ftwT[(size_t)s_list[seg][j + 0] * MDIM + tid];
            const float a1 = g_ftwT[(size_t)s_list[seg][j + 1] * MDIM + tid];
            const float a2 = g_ftwT[(size_t)s_list[seg][j + 2] * MDIM + tid];
            const float a3 = g_ftwT[(size_t)s_list[seg][j + 3] * MDIM + tid];
            acc += a0; acc += a1; acc += a2; acc += a3;
        }
        for (; j < n; j++)
            acc += g_ftwT[(size_t)s_list[seg][j] * MDIM + tid];
        if (seg < 2) accW += acc; else accB += acc;
    }

    // stm blend + clip
    const float s  = stm[b];
    s_h[tid]       = clamp01(s * accW + (1.0f - s) * accB);
    s_h[256 + tid] = clamp01(s * accB + (1.0f - s) * accW);
    __syncthreads();

    // L1: 512 -> 32. Output n = tid>>3; 8 threads per output.
    {
        const int n   = tid >> 3;
        const int seg = tid & 7;
        const float4* wrow = reinterpret_cast<const float4*>(l1_w + n * 512 + seg * 64);
        const float4* hv   = reinterpret_cast<const float4*>(s_h) + seg * 16;
        float psum = 0.0f;
        #pragma unroll
        for (int i = 0; i < 16; i++) {
            const float4 a = wrow[i];
            const float4 x = hv[i];
            psum += a.x * x.x;
            psum += a.y * x.y;
            psum += a.z * x.z;
            psum += a.w * x.w;
        }
        psum += __shfl_down_sync(0xffffffffu, psum, 4);
        psum += __shfl_down_sync(0xffffffffu, psum, 2);
        psum += __shfl_down_sync(0xffffffffu, psum, 1);
        if (seg == 0) s_l2x[n] = clamp01(psum + l1_b[n]);
    }
    __syncthreads();

    // L2 (32->32), L3 (32->1), eval scaling. Warp 0 only.
    if (tid < 32) {
        float q = l2_b[tid];
        #pragma unroll
        for (int k = 0; k < 32; k++) q += l2_w[tid * 32 + k] * s_l2x[k];
        const float l3x = clamp01(q);
        float t = l3x * l3_w[tid];
        #pragma unroll
        for (int off = 16; off > 0; off >>= 1)
            t += __shfl_down_sync(0xffffffffu, t, off);
        if (tid == 0) {
            const float ev = clamp01(t + l3_b[0]);
            out[b] = (ev - 0.5f) * 2.0f * 10000.0f;
        }
    }
}

// ---------------------------------------------------------------------------
// Launch
// ---------------------------------------------------------------------------
extern "C" void kernel_launch(void* const* d_in, const int* in_sizes, int n_in,
                              void* d_out, int out_size)
{
    const float* wf    = (const float*)d_in[0];
    const float* bfeat = (const float*)d_in[1];
    const float* stm   = (const float*)d_in[2];
    const float* ft_w  = (const float*)d_in[3];
    const float* ft_b  = (const float*)d_in[4];
    const float* l1_w  = (const float*)d_in[5];
    const float* l1_b  = (const float*)d_in[6];
    const float* l2_w  = (const float*)d_in[7];
    const float* l2_b  = (const float*)d_in[8];
    const float* l3_w  = (const float*)d_in[9];
    const float* l3_b  = (const float*)d_in[10];
    float* out = (float*)d_out;

    // 1) Transpose ft_w -> g_ftwT (gather table)
    dim3 tgrid(NF / 32, MDIM / 32);
    transpose_ftw_kernel<<<tgrid, 256>>>(ft_w);

    // 2) Phase A: pure streaming scan (8192 warps, one per half-row)
    scan_kernel<<<(ROWS * PARTS) / 8, 256>>>(wf, bfeat);

    // 3) Phase B: gather + MLP tail, one CTA per position
    gather_mlp_kernel<<<NB, 256>>>(stm, ft_b, l1_w, l1_b, l2_w, l2_b,
                                   l3_w, l3_b, out);
}